// round 17
// baseline (speedup 1.0000x reference)
#include <cuda_runtime.h>
#include <cuda_bf16.h>
#include <cstdint>

#define T_SEQ 512
#define BATCH 1024
#define DIN   32
#define HDIM  64
#define G     256     // 4*H gate rows
#define NB    8       // batches per CTA
#define NTHR  256     // A: warps 0-3 (layer 0 + x-part), B: warps 4-7 (layer 1)
#define W0_S  36      // sW0b row stride in 32-bit words (144B = 16*9, 9 odd)
#define W1_S  68      // sW1b row stride in 32-bit words (272B = 16*17, 17 odd)
#define XP_S  9       // x-part exchange stride: coprime 32 -> conflict-free

// smem words: sW0b 256*36=9216 | sW1b 256*68=17408 | xp 2*2304 | xsb 2*256
//             h0T 1024 | h1T 512   = 33280 words = 133120 B
#define SMEM_WORDS (G*W0_S + G*W1_S + 2*(G*XP_S) + 2*(NB*DIN) + 2*(NB*64) + NB*64)

__device__ __forceinline__ unsigned long long pack2(float lo, float hi) {
    unsigned long long r;
    asm("mov.b64 %0, {%1,%2};" : "=l"(r) : "f"(lo), "f"(hi));
    return r;
}
__device__ __forceinline__ void fma2(unsigned long long& d,
                                     unsigned long long a, unsigned long long b) {
    asm("fma.rn.f32x2 %0, %1, %2, %0;" : "+l"(d) : "l"(a), "l"(b));
}
__device__ __forceinline__ float hsum2(unsigned long long v) {
    float lo, hi;
    asm("mov.b64 {%0,%1}, %2;" : "=f"(lo), "=f"(hi) : "l"(v));
    return lo + hi;
}
// bf16x2 word -> f32x2 operand (exact): f_lo = w<<16, f_hi = w & 0xFFFF0000
__device__ __forceinline__ unsigned long long bfpair(uint32_t w) {
    unsigned long long r;
    uint32_t lo = w << 16;
    uint32_t hi = w & 0xFFFF0000u;
    asm("mov.b64 %0, {%1,%2};" : "=l"(r) : "r"(lo), "r"(hi));
    return r;
}
__device__ __forceinline__ uint32_t pack_bf(float a, float b) {
    __nv_bfloat162 t = __floats2bfloat162_rn(a, b);   // .x = a (low half)
    return *reinterpret_cast<uint32_t*>(&t);
}
// HW tanh (sm_75+): single MUFU op
__device__ __forceinline__ float tanh_hw(float x) {
    float y;
    asm("tanh.approx.f32 %0, %1;" : "=f"(y) : "f"(x));
    return y;
}
__device__ __forceinline__ float sigmoid_hw(float x) {
    return fmaf(tanh_hw(0.5f * x), 0.5f, 0.5f);
}
__device__ __forceinline__ void bar_sync(int id, int cnt) {
    asm volatile("bar.sync %0, %1;" :: "r"(id), "r"(cnt) : "memory");
}
__device__ __forceinline__ void bar_arrive(int id, int cnt) {
    asm volatile("bar.arrive %0, %1;" :: "r"(id), "r"(cnt) : "memory");
}

extern __shared__ uint32_t smem_u[];

__global__ void __launch_bounds__(NTHR, 1)
lstm_return_kernel(const float* __restrict__ x,
                   const float* __restrict__ Wih0, const float* __restrict__ Whh0,
                   const float* __restrict__ bih0, const float* __restrict__ bhh0,
                   const float* __restrict__ Wih1, const float* __restrict__ Whh1,
                   const float* __restrict__ bih1, const float* __restrict__ bhh1,
                   const float* __restrict__ W1,   const float* __restrict__ b1,
                   const float* __restrict__ W2,   const float* __restrict__ b2,
                   float* __restrict__ out)
{
    uint32_t* sW0b = smem_u;                 // [256][36] words, bf16x2 Whh0
    uint32_t* sW1b = sW0b + G * W0_S;        // [256][68] words, bf16x2 [Wih1|Whh1]
    float* xp  = (float*)(sW1b + G * W1_S);  // [2][256][9] x-part (incl. bias0)
    float* xsb = xp  + 2 * G * XP_S;         // [2][8][32]  x staging
    float* h0T = xsb + 2 * NB * DIN;         // [2][16][8][4] h0 transposed
    float* h1T = h0T + 2 * 512;              // [16][8][4]    h1 transposed

    const int tid   = threadIdx.x;
    const int l     = tid & 31;
    const bool grpA = (tid < 128);
    const int gw    = (tid >> 5) & 3;        // warp index within group
    const int rq    = gw * 16 + (l & 15);    // owned unit (rows rq+64m)
    const int bg    = l >> 4;                // batch half
    const int bbase = blockIdx.x * NB;

    // ---- stage weights as bf16 ----
    for (int i = tid; i < G * 32; i += NTHR) {          // Whh0: 32 words/row
        int r = i >> 5, w = i & 31;
        sW0b[r * W0_S + w] = pack_bf(Whh0[r * 64 + 2 * w], Whh0[r * 64 + 2 * w + 1]);
    }
    for (int i = tid; i < G * 64; i += NTHR) {          // [Wih1|Whh1]: 64 words/row
        int r = i >> 6, w = i & 63;
        float a, b;
        if (w < 32) { a = Wih1[r * 64 + 2 * w];        b = Wih1[r * 64 + 2 * w + 1]; }
        else        { a = Whh1[r * 64 + 2 * (w - 32)]; b = Whh1[r * 64 + 2 * (w - 32) + 1]; }
        sW1b[r * W1_S + w] = pack_bf(a, b);
    }
    for (int i = tid; i < 3 * 512; i += NTHR) h0T[i] = 0.0f;   // h0T + h1T

    // ---- A: Wih0 row-pair (jx, jx+128) in fp32 registers ----
    const int jx = tid;
    unsigned long long wx0[16], wx1[16];
#pragma unroll
    for (int k = 0; k < 16; k++) {
        int r0 = jx * DIN + 2 * k, r1 = (jx + 128) * DIN + 2 * k;
        wx0[k] = grpA ? pack2(Wih0[r0], Wih0[r0 + 1]) : 0ull;
        wx1[k] = grpA ? pack2(Wih0[r1], Wih0[r1 + 1]) : 0ull;
    }
    float bxa = 0.f, bxb = 0.f;
    if (grpA) { bxa = bih0[jx] + bhh0[jx]; bxb = bih0[jx + 128] + bhh0[jx + 128]; }

    float bs1[4];
#pragma unroll
    for (int m = 0; m < 4; m++)
        bs1[m] = grpA ? 0.0f : (bih1[rq + 64 * m] + bhh1[rq + 64 * m]);

    float cst[4] = {0.f, 0.f, 0.f, 0.f};

    // x staging (A): thread -> (batch xb, channels xc, xc+1)
    const int xb = tid >> 4, xc = (tid & 15) * 2;
    const float* xptr = x + ((size_t)(bbase + (xb & 7)) * T_SEQ) * DIN + xc;
    float2 xcur = make_float2(0.f, 0.f);
    if (grpA) {
        *(float2*)(xsb + 0 * 256 + xb * DIN + xc) = *(const float2*)(xptr);
        *(float2*)(xsb + 1 * 256 + xb * DIN + xc) = *(const float2*)(xptr + DIN);
        xcur = *(const float2*)(xptr + 2 * DIN);
    }

    const int wr0w = rq * W0_S, wr1w = rq * W1_S;

    __syncthreads();   // weights, zeros, xsb visible

    if (grpA) {
        auto xpart = [&](int buf) {
            const float* xsp = xsb + buf * 256;
            float* xpd = xp + buf * (G * XP_S);
            unsigned long long a0[NB], a1[NB];
#pragma unroll
            for (int b = 0; b < NB; b++) { a0[b] = pack2(bxa, 0.f); a1[b] = pack2(bxb, 0.f); }
#pragma unroll
            for (int kc = 0; kc < 8; kc++) {
                const unsigned long long u0 = wx0[2*kc], u1 = wx0[2*kc+1];
                const unsigned long long v0 = wx1[2*kc], v1 = wx1[2*kc+1];
#pragma unroll
                for (int b = 0; b < NB; b++) {
                    ulonglong2 iv = *(const ulonglong2*)(xsp + b * DIN + 4 * kc);
                    fma2(a0[b], u0, iv.x); fma2(a0[b], u1, iv.y);
                    fma2(a1[b], v0, iv.x); fma2(a1[b], v1, iv.y);
                }
            }
#pragma unroll
            for (int b = 0; b < NB; b++) {
                xpd[jx * XP_S + b]         = hsum2(a0[b]);
                xpd[(jx + 128) * XP_S + b] = hsum2(a1[b]);
            }
        };

        xpart(0);
        bar_sync(5, 128);

        // =========================== GROUP A: layer 0 ===========================
        for (int t = 0; t < T_SEQ; t++) {
            const int p = t & 1;
            const float* xpc = xp + p * (G * XP_S);
            unsigned long long acc[16];
#pragma unroll
            for (int m = 0; m < 4; m++)
#pragma unroll
                for (int q = 0; q < 4; q++)
                    acc[m * 4 + q] = pack2(xpc[(rq + 64 * m) * XP_S + bg * 4 + q], 0.f);
            const float* h0p = h0T + (p ^ 1) * 512;
            // h-part: bf16 weights, 8 k-chunks of 8
#pragma unroll
            for (int kc = 0; kc < 8; kc++) {
                uint4 u0 = *(const uint4*)(sW0b + wr0w +   0 * W0_S + kc * 4);
                uint4 u1 = *(const uint4*)(sW0b + wr0w +  64 * W0_S + kc * 4);
                uint4 u2 = *(const uint4*)(sW0b + wr0w + 128 * W0_S + kc * 4);
                uint4 u3 = *(const uint4*)(sW0b + wr0w + 192 * W0_S + kc * 4);
                unsigned long long w0a = bfpair(u0.x), w0b = bfpair(u0.y), w0c = bfpair(u0.z), w0d = bfpair(u0.w);
                unsigned long long w1a = bfpair(u1.x), w1b = bfpair(u1.y), w1c = bfpair(u1.z), w1d = bfpair(u1.w);
                unsigned long long w2a = bfpair(u2.x), w2b = bfpair(u2.y), w2c = bfpair(u2.z), w2d = bfpair(u2.w);
                unsigned long long w3a = bfpair(u3.x), w3b = bfpair(u3.y), w3c = bfpair(u3.z), w3d = bfpair(u3.w);
#pragma unroll
                for (int q = 0; q < 4; q++) {
                    int bq = bg * 4 + q;
                    ulonglong2 iv0 = *(const ulonglong2*)(h0p + (2 * kc)     * 32 + bq * 4);
                    ulonglong2 iv1 = *(const ulonglong2*)(h0p + (2 * kc + 1) * 32 + bq * 4);
                    fma2(acc[0*4+q], w0a, iv0.x); fma2(acc[0*4+q], w0b, iv0.y);
                    fma2(acc[0*4+q], w0c, iv1.x); fma2(acc[0*4+q], w0d, iv1.y);
                    fma2(acc[1*4+q], w1a, iv0.x); fma2(acc[1*4+q], w1b, iv0.y);
                    fma2(acc[1*4+q], w1c, iv1.x); fma2(acc[1*4+q], w1d, iv1.y);
                    fma2(acc[2*4+q], w2a, iv0.x); fma2(acc[2*4+q], w2b, iv0.y);
                    fma2(acc[2*4+q], w2c, iv1.x); fma2(acc[2*4+q], w2d, iv1.y);
                    fma2(acc[3*4+q], w3a, iv0.x); fma2(acc[3*4+q], w3b, iv0.y);
                    fma2(acc[3*4+q], w3c, iv1.x); fma2(acc[3*4+q], w3d, iv1.y);
                }
            }
            if (t >= 2) bar_sync(3 + p, NTHR);   // h0T[p] free (B consumed t-2)
            float* h0c = h0T + p * 512;
#pragma unroll
            for (int q = 0; q < 4; q++) {
                float i_ = sigmoid_hw(hsum2(acc[0 * 4 + q]));
                float f_ = sigmoid_hw(hsum2(acc[1 * 4 + q]));
                float g_ = tanh_hw(hsum2(acc[2 * 4 + q]));
                float o_ = sigmoid_hw(hsum2(acc[3 * 4 + q]));
                cst[q] = f_ * cst[q] + i_ * g_;
                float h = o_ * tanh_hw(cst[q]);
                h0c[(rq >> 2) * 32 + (bg * 4 + q) * 4 + (rq & 3)] = h;
            }
            bar_arrive(1 + p, NTHR);             // h0(t) ready for B

            if (t + 2 < T_SEQ) {
                *(float2*)(xsb + p * 256 + xb * DIN + xc) = xcur;
                if (t + 3 < T_SEQ) xcur = *(const float2*)(xptr + (size_t)(t + 3) * DIN);
            }
            if (t + 1 < T_SEQ) xpart(p ^ 1);
            bar_sync(5, 128);                    // xp, xsb, h0T[p] visible within A
        }
    } else {
        // =========================== GROUP B: layer 1 ===========================
        for (int t = 0; t < T_SEQ; t++) {
            const int p = t & 1;
            bar_sync(1 + p, NTHR);               // wait h0(t); orders h1T too
            const float* h0p = h0T + p * 512;

            unsigned long long acc[16];
#pragma unroll
            for (int m = 0; m < 4; m++)
#pragma unroll
                for (int q = 0; q < 4; q++) acc[m * 4 + q] = pack2(bs1[m], 0.0f);
            // part 1: h0 @ Wih1^T (bf16 words 0..31)
#pragma unroll
            for (int kc = 0; kc < 8; kc++) {
                uint4 u0 = *(const uint4*)(sW1b + wr1w +   0 * W1_S + kc * 4);
                uint4 u1 = *(const uint4*)(sW1b + wr1w +  64 * W1_S + kc * 4);
                uint4 u2 = *(const uint4*)(sW1b + wr1w + 128 * W1_S + kc * 4);
                uint4 u3 = *(const uint4*)(sW1b + wr1w + 192 * W1_S + kc * 4);
                unsigned long long w0a = bfpair(u0.x), w0b = bfpair(u0.y), w0c = bfpair(u0.z), w0d = bfpair(u0.w);
                unsigned long long w1a = bfpair(u1.x), w1b = bfpair(u1.y), w1c = bfpair(u1.z), w1d = bfpair(u1.w);
                unsigned long long w2a = bfpair(u2.x), w2b = bfpair(u2.y), w2c = bfpair(u2.z), w2d = bfpair(u2.w);
                unsigned long long w3a = bfpair(u3.x), w3b = bfpair(u3.y), w3c = bfpair(u3.z), w3d = bfpair(u3.w);
#pragma unroll
                for (int q = 0; q < 4; q++) {
                    int bq = bg * 4 + q;
                    ulonglong2 iv0 = *(const ulonglong2*)(h0p + (2 * kc)     * 32 + bq * 4);
                    ulonglong2 iv1 = *(const ulonglong2*)(h0p + (2 * kc + 1) * 32 + bq * 4);
                    fma2(acc[0*4+q], w0a, iv0.x); fma2(acc[0*4+q], w0b, iv0.y);
                    fma2(acc[0*4+q], w0c, iv1.x); fma2(acc[0*4+q], w0d, iv1.y);
                    fma2(acc[1*4+q], w1a, iv0.x); fma2(acc[1*4+q], w1b, iv0.y);
                    fma2(acc[1*4+q], w1c, iv1.x); fma2(acc[1*4+q], w1d, iv1.y);
                    fma2(acc[2*4+q], w2a, iv0.x); fma2(acc[2*4+q], w2b, iv0.y);
                    fma2(acc[2*4+q], w2c, iv1.x); fma2(acc[2*4+q], w2d, iv1.y);
                    fma2(acc[3*4+q], w3a, iv0.x); fma2(acc[3*4+q], w3b, iv0.y);
                    fma2(acc[3*4+q], w3c, iv1.x); fma2(acc[3*4+q], w3d, iv1.y);
                }
            }
            bar_arrive(3 + p, NTHR);             // h0T[p] consumed
            // part 2: h1 @ Whh1^T (bf16 words 32..63)
#pragma unroll
            for (int kc = 0; kc < 8; kc++) {
                uint4 u0 = *(const uint4*)(sW1b + wr1w +   0 * W1_S + 32 + kc * 4);
                uint4 u1 = *(const uint4*)(sW1b + wr1w +  64 * W1_S + 32 + kc * 4);
                uint4 u2 = *(const uint4*)(sW1b + wr1w + 128 * W1_S + 32 + kc * 4);
                uint4 u3 = *(const uint4*)(sW1b + wr1w + 192 * W1_S + 32 + kc * 4);
                unsigned long long w0a = bfpair(u0.x), w0b = bfpair(u0.y), w0c = bfpair(u0.z), w0d = bfpair(u0.w);
                unsigned long long w1a = bfpair(u1.x), w1b = bfpair(u1.y), w1c = bfpair(u1.z), w1d = bfpair(u1.w);
                unsigned long long w2a = bfpair(u2.x), w2b = bfpair(u2.y), w2c = bfpair(u2.z), w2d = bfpair(u2.w);
                unsigned long long w3a = bfpair(u3.x), w3b = bfpair(u3.y), w3c = bfpair(u3.z), w3d = bfpair(u3.w);
#pragma unroll
                for (int q = 0; q < 4; q++) {
                    int bq = bg * 4 + q;
                    ulonglong2 iv0 = *(const ulonglong2*)(h1T + (2 * kc)     * 32 + bq * 4);
                    ulonglong2 iv1 = *(const ulonglong2*)(h1T + (2 * kc + 1) * 32 + bq * 4);
                    fma2(acc[0*4+q], w0a, iv0.x); fma2(acc[0*4+q], w0b, iv0.y);
                    fma2(acc[0*4+q], w0c, iv1.x); fma2(acc[0*4+q], w0d, iv1.y);
                    fma2(acc[1*4+q], w1a, iv0.x); fma2(acc[1*4+q], w1b, iv0.y);
                    fma2(acc[1*4+q], w1c, iv1.x); fma2(acc[1*4+q], w1d, iv1.y);
                    fma2(acc[2*4+q], w2a, iv0.x); fma2(acc[2*4+q], w2b, iv0.y);
                    fma2(acc[2*4+q], w2c, iv1.x); fma2(acc[2*4+q], w2d, iv1.y);
                    fma2(acc[3*4+q], w3a, iv0.x); fma2(acc[3*4+q], w3b, iv0.y);
                    fma2(acc[3*4+q], w3c, iv1.x); fma2(acc[3*4+q], w3d, iv1.y);
                }
            }
#pragma unroll
            for (int q = 0; q < 4; q++) {
                float i_ = sigmoid_hw(hsum2(acc[0 * 4 + q]));
                float f_ = sigmoid_hw(hsum2(acc[1 * 4 + q]));
                float g_ = tanh_hw(hsum2(acc[2 * 4 + q]));
                float o_ = sigmoid_hw(hsum2(acc[3 * 4 + q]));
                cst[q] = f_ * cst[q] + i_ * g_;
                h1T[(rq >> 2) * 32 + (bg * 4 + q) * 4 + (rq & 3)] = o_ * tanh_hw(cst[q]);
            }
            // h1T write->read for t+1 ordered by bar_sync(1+p') full-CTA rendezvous
        }
    }

    __syncthreads();   // final h1 visible to all

    // ===== head: out = relu(h1 @ W1^T + b1) @ W2^T + b2 (fp32 throughout) =====
    {
        const int hb = tid >> 5;
        const int hu = tid & 31;
        const float* w1r = W1 + hu * HDIM;
        float acc = b1[hu];
#pragma unroll
        for (int k = 0; k < HDIM; k++)
            acc += w1r[k] * h1T[(k >> 2) * 32 + hb * 4 + (k & 3)];
        acc = fmaxf(acc, 0.0f) * W2[hu];
        ((float*)smem_u)[hb * 32 + hu] = acc;   // reuse smem as scratch
    }
    __syncthreads();
    if (tid < NB) {
        float s = b2[0];
#pragma unroll
        for (int u = 0; u < 32; u++) s += ((float*)smem_u)[tid * 32 + u];
        out[bbase + tid] = s;
    }
}

extern "C" void kernel_launch(void* const* d_in, const int* in_sizes, int n_in,
                              void* d_out, int out_size) {
    (void)in_sizes; (void)n_in; (void)out_size;
    const float* x    = (const float*)d_in[0];
    const float* Wih0 = (const float*)d_in[1];
    const float* Whh0 = (const float*)d_in[2];
    const float* bih0 = (const float*)d_in[3];
    const float* bhh0 = (const float*)d_in[4];
    const float* Wih1 = (const float*)d_in[5];
    const float* Whh1 = (const float*)d_in[6];
    const float* bih1 = (const float*)d_in[7];
    const float* bhh1 = (const float*)d_in[8];
    const float* W1   = (const float*)d_in[9];
    const float* b1   = (const float*)d_in[10];
    const float* W2   = (const float*)d_in[11];
    const float* b2   = (const float*)d_in[12];
    float* out = (float*)d_out;

    const size_t smem_bytes = (size_t)SMEM_WORDS * sizeof(uint32_t);
    cudaFuncSetAttribute(lstm_return_kernel,
                         cudaFuncAttributeMaxDynamicSharedMemorySize,
                         (int)smem_bytes);
    lstm_return_kernel<<<BATCH / NB, NTHR, smem_bytes>>>(
        x, Wih0, Whh0, bih0, bhh0, Wih1, Whh1, bih1, bhh1,
        W1, b1, W2, b2, out);
}